// round 1
// baseline (speedup 1.0000x reference)
#include <cuda_runtime.h>
#include <cuda_bf16.h>
#include <cstdint>

// ---------------------------------------------------------------------------
// TriXLinear: out = (x @ sign(W)^T) * scales * tile_gate_mask
//   x:      [4096, 4096] f32
//   gate:   [4096, 4]    i32 (0/1), tile t masks output cols [t*1024,(t+1)*1024)
//   weight: [4096, 4096] f32 (entries are +-1)
//   scales: [4096]       f32
//   out:    [4096, 4096] f32
//
// Strategy: bf16 hi/lo split of x (error ~2^-18) + bf16 +-1 weights, fp32
// accumulation via mma.sync.m16n8k16. Fused scale+gate epilogue.
// ---------------------------------------------------------------------------

#define M_DIM 4096
#define N_DIM 4096
#define K_DIM 4096
#define NUM_TILES 4
#define TILE_SZ (N_DIM / NUM_TILES)

#define BM 128
#define BN 128
#define BK 32
#define PAD_K 56              // padded smem row stride (bf16 elems); 112B rows:
                              // 16B-aligned & conflict-free ldmatrix (28*r mod 32 distinct)
#define NKT (K_DIM / BK)      // 128 k-tiles

// scratch (allowed: __device__ globals, no runtime allocation)
__device__ __nv_bfloat16 g_Wb [(size_t)N_DIM * K_DIM];
__device__ __nv_bfloat16 g_Xhi[(size_t)M_DIM * K_DIM];
__device__ __nv_bfloat16 g_Xlo[(size_t)M_DIM * K_DIM];

// ---------------------------- prep kernels --------------------------------

__global__ void prep_w_kernel(const float* __restrict__ w) {
    size_t i = ((size_t)blockIdx.x * blockDim.x + threadIdx.x) * 4;
    float4 v = *reinterpret_cast<const float4*>(w + i);
    __nv_bfloat16 o[4];
    o[0] = __float2bfloat16((v.x > 0.f) ? 1.f : ((v.x < 0.f) ? -1.f : 0.f));
    o[1] = __float2bfloat16((v.y > 0.f) ? 1.f : ((v.y < 0.f) ? -1.f : 0.f));
    o[2] = __float2bfloat16((v.z > 0.f) ? 1.f : ((v.z < 0.f) ? -1.f : 0.f));
    o[3] = __float2bfloat16((v.w > 0.f) ? 1.f : ((v.w < 0.f) ? -1.f : 0.f));
    *reinterpret_cast<uint2*>(g_Wb + i) = *reinterpret_cast<uint2*>(o);
}

__global__ void prep_x_kernel(const float* __restrict__ x) {
    size_t i = ((size_t)blockIdx.x * blockDim.x + threadIdx.x) * 4;
    float4 v = *reinterpret_cast<const float4*>(x + i);
    __nv_bfloat16 hi[4], lo[4];
    float f[4] = {v.x, v.y, v.z, v.w};
#pragma unroll
    for (int j = 0; j < 4; j++) {
        hi[j] = __float2bfloat16(f[j]);
        lo[j] = __float2bfloat16(f[j] - __bfloat162float(hi[j]));
    }
    *reinterpret_cast<uint2*>(g_Xhi + i) = *reinterpret_cast<uint2*>(hi);
    *reinterpret_cast<uint2*>(g_Xlo + i) = *reinterpret_cast<uint2*>(lo);
}

// ---------------------------- GEMM helpers --------------------------------

__device__ __forceinline__ uint32_t sptr(const void* p) {
    return (uint32_t)__cvta_generic_to_shared(p);
}

__device__ __forceinline__ void ldm_x4(uint32_t& r0, uint32_t& r1,
                                       uint32_t& r2, uint32_t& r3,
                                       uint32_t addr) {
    asm volatile("ldmatrix.sync.aligned.m8n8.x4.shared.b16 {%0,%1,%2,%3}, [%4];"
                 : "=r"(r0), "=r"(r1), "=r"(r2), "=r"(r3)
                 : "r"(addr));
}

__device__ __forceinline__ void mma16816(float* c, uint32_t a0, uint32_t a1,
                                         uint32_t a2, uint32_t a3,
                                         uint32_t b0, uint32_t b1) {
    asm volatile(
        "mma.sync.aligned.m16n8k16.row.col.f32.bf16.bf16.f32 "
        "{%0,%1,%2,%3}, {%4,%5,%6,%7}, {%8,%9}, {%0,%1,%2,%3};"
        : "+f"(c[0]), "+f"(c[1]), "+f"(c[2]), "+f"(c[3])
        : "r"(a0), "r"(a1), "r"(a2), "r"(a3), "r"(b0), "r"(b1));
}

// ---------------------------- GEMM kernel ---------------------------------
// grid (32, 32), 256 threads. Warp layout 4(M) x 2(N): warp tile 32x64.

__global__ __launch_bounds__(256, 1) void trix_gemm_kernel(
    const int* __restrict__ gate,
    const float* __restrict__ scales,
    float* __restrict__ out) {
    __shared__ __nv_bfloat16 sHi[BM * PAD_K];
    __shared__ __nv_bfloat16 sLo[BM * PAD_K];
    __shared__ __nv_bfloat16 sW [BN * PAD_K];

    const int tid  = threadIdx.x;
    const int warp = tid >> 5;
    const int lane = tid & 31;
    const int wm   = warp & 3;   // 0..3 -> M offset wm*32
    const int wn   = warp >> 2;  // 0..1 -> N offset wn*64
    const int m0   = blockIdx.y * BM;
    const int n0   = blockIdx.x * BN;

    // global load mapping: each thread loads 2 rows (lr, lr+64) x one uint4
    const int lr = tid >> 2;     // 0..63
    const int lc = tid & 3;      // uint4 column group (8 bf16 each)

    const uint4* pHi = reinterpret_cast<const uint4*>(g_Xhi);
    const uint4* pLo = reinterpret_cast<const uint4*>(g_Xlo);
    const uint4* pW  = reinterpret_cast<const uint4*>(g_Wb);
    const size_t rowU4 = K_DIM / 8;  // 512 uint4 per row

    float acc[2][8][4];
#pragma unroll
    for (int a = 0; a < 2; a++)
#pragma unroll
        for (int b = 0; b < 8; b++)
#pragma unroll
            for (int c = 0; c < 4; c++) acc[a][b][c] = 0.f;

    // ldmatrix address precomputation
    const int g       = lane >> 3;          // group 0..3
    const int gl      = lane & 7;
    const int a_row   = (g & 1) * 8 + gl;   // A: row_off within 16, +8 for k-high via g>>1
    const int a_koff  = (g >> 1) * 8;
    const int b_nrow  = (g >> 1) * 8 + gl;  // B: n_off within 16
    const int b_koff  = (g & 1) * 8;

    uint4 r[6];
    // load k-tile into regs
    auto load_tile = [&](int kt, uint4* rr) {
        size_t a0i = (size_t)(m0 + lr) * rowU4 + (size_t)kt * 4 + lc;
        size_t a1i = a0i + (size_t)64 * rowU4;
        size_t w0i = (size_t)(n0 + lr) * rowU4 + (size_t)kt * 4 + lc;
        rr[0] = pHi[a0i];
        rr[1] = pHi[a1i];
        rr[2] = pLo[a0i];
        rr[3] = pLo[a1i];
        rr[4] = pW[w0i];
        rr[5] = pW[w0i + (size_t)64 * rowU4];
    };
    auto store_tile = [&](uint4* rr) {
        *reinterpret_cast<uint4*>(sHi + lr * PAD_K + lc * 8)        = rr[0];
        *reinterpret_cast<uint4*>(sHi + (lr + 64) * PAD_K + lc * 8) = rr[1];
        *reinterpret_cast<uint4*>(sLo + lr * PAD_K + lc * 8)        = rr[2];
        *reinterpret_cast<uint4*>(sLo + (lr + 64) * PAD_K + lc * 8) = rr[3];
        *reinterpret_cast<uint4*>(sW  + lr * PAD_K + lc * 8)        = rr[4];
        *reinterpret_cast<uint4*>(sW  + (lr + 64) * PAD_K + lc * 8) = rr[5];
    };

    load_tile(0, r);
    store_tile(r);
    __syncthreads();

    for (int kt = 0; kt < NKT; kt++) {
        uint4 nr[6];
        if (kt + 1 < NKT) load_tile(kt + 1, nr);

        // compute current tile from smem
#pragma unroll
        for (int kk = 0; kk < BK; kk += 16) {
            uint32_t ah[2][4], al[2][4], bf[8][2];
#pragma unroll
            for (int ms = 0; ms < 2; ms++) {
                int row = wm * 32 + ms * 16 + a_row;
                ldm_x4(ah[ms][0], ah[ms][1], ah[ms][2], ah[ms][3],
                       sptr(sHi + row * PAD_K + kk + a_koff));
                ldm_x4(al[ms][0], al[ms][1], al[ms][2], al[ms][3],
                       sptr(sLo + row * PAD_K + kk + a_koff));
            }
#pragma unroll
            for (int np = 0; np < 4; np++) {
                int nrow = wn * 64 + np * 16 + b_nrow;
                ldm_x4(bf[np * 2][0], bf[np * 2][1], bf[np * 2 + 1][0], bf[np * 2 + 1][1],
                       sptr(sW + nrow * PAD_K + kk + b_koff));
            }
#pragma unroll
            for (int ms = 0; ms < 2; ms++) {
#pragma unroll
                for (int ns = 0; ns < 8; ns++) {
                    mma16816(acc[ms][ns], ah[ms][0], ah[ms][1], ah[ms][2], ah[ms][3],
                             bf[ns][0], bf[ns][1]);
                    mma16816(acc[ms][ns], al[ms][0], al[ms][1], al[ms][2], al[ms][3],
                             bf[ns][0], bf[ns][1]);
                }
            }
        }

        __syncthreads();
        if (kt + 1 < NKT) {
            store_tile(nr);
            __syncthreads();
        }
    }

    // epilogue: scale + gate mask, write f32
#pragma unroll
    for (int ms = 0; ms < 2; ms++) {
        int row_lo = m0 + wm * 32 + ms * 16 + (lane >> 2);
#pragma unroll
        for (int half = 0; half < 2; half++) {
            int row = row_lo + half * 8;
            const int* grow = gate + (size_t)row * NUM_TILES;
#pragma unroll
            for (int ns = 0; ns < 8; ns++) {
                int col = n0 + wn * 64 + ns * 8 + (lane & 3) * 2;
                float gmask = (float)grow[col >> 10];  // TILE_SZ = 1024
                float2 v;
                v.x = acc[ms][ns][half * 2 + 0] * scales[col]     * gmask;
                v.y = acc[ms][ns][half * 2 + 1] * scales[col + 1] * gmask;
                *reinterpret_cast<float2*>(out + (size_t)row * N_DIM + col) = v;
            }
        }
    }
}

// ---------------------------- launch ---------------------------------------

extern "C" void kernel_launch(void* const* d_in, const int* in_sizes, int n_in,
                              void* d_out, int out_size) {
    const float* x      = (const float*)d_in[0];  // [4096,4096] f32
    const int*   gate   = (const int*)d_in[1];    // [4096,4]    i32
    const float* weight = (const float*)d_in[2];  // [4096,4096] f32
    const float* scales = (const float*)d_in[3];  // [4096]      f32
    float* out = (float*)d_out;

    const size_t total = (size_t)M_DIM * K_DIM;   // 16777216
    const int threads = 256;
    const int blocks4 = (int)(total / 4 / threads);  // 4 elems/thread

    prep_w_kernel<<<blocks4, threads>>>(weight);
    prep_x_kernel<<<blocks4, threads>>>(x);

    dim3 grid(N_DIM / BN, M_DIM / BM);  // (32, 32)
    trix_gemm_kernel<<<grid, 256>>>(gate, scales, out);
}